// round 7
// baseline (speedup 1.0000x reference)
#include <cuda_runtime.h>
#include <cstdint>

// Problem constants
#define B_ROWS 8192
#define D_DIM  1024
#define G_REP  8
#define N_TOT  (B_ROWS * D_DIM)          // 8,388,608 elements of xf
#define OUT_ROW (G_REP * D_DIM)          // 8192 floats per output row
#define EPS 1e-12f

#define SUM_BLOCKS 1184                  // 148 SMs * 8

// Scratch (no allocations allowed -> __device__ globals)
__device__ double       g_part[SUM_BLOCKS];
__device__ float        g_mean;
__device__ unsigned int g_count;         // zero-init; last block resets -> replay-safe

// ---------------------------------------------------------------------------
// Kernel 1: global sum of xf. Per-block partial (double), last-block ticket
// reduces partials -> g_mean, then resets the ticket counter. No k_reset
// kernel needed (saves a ~3.6us graph node).
// ---------------------------------------------------------------------------
__global__ __launch_bounds__(256) void k_sum(const float* __restrict__ xf) {
    const int n4 = N_TOT / 4;
    const float4* __restrict__ x4 = reinterpret_cast<const float4*>(xf);

    double local = 0.0;
    int idx    = blockIdx.x * blockDim.x + threadIdx.x;
    int stride = gridDim.x * blockDim.x;
    for (int i = idx; i < n4; i += stride) {
        float4 v = __ldg(&x4[i]);
        local += (double)((v.x + v.y) + (v.z + v.w));
    }

    // warp reduce
    #pragma unroll
    for (int o = 16; o > 0; o >>= 1)
        local += __shfl_down_sync(0xffffffffu, local, o);

    __shared__ double smem[8];
    __shared__ bool   s_last;
    int lane = threadIdx.x & 31;
    int warp = threadIdx.x >> 5;
    if (lane == 0) smem[warp] = local;
    if (threadIdx.x == 0) s_last = false;
    __syncthreads();

    if (threadIdx.x == 0) {
        double blk = smem[0] + smem[1] + smem[2] + smem[3]
                   + smem[4] + smem[5] + smem[6] + smem[7];
        g_part[blockIdx.x] = blk;
        __threadfence();                              // partial visible before ticket
        unsigned int t = atomicAdd(&g_count, 1u);
        s_last = (t == (unsigned)(gridDim.x - 1));
    }
    __syncthreads();

    if (s_last) {
        // All 256 threads of the last block reduce the 1184 partials.
        double s = 0.0;
        for (int i = threadIdx.x; i < SUM_BLOCKS; i += 256)
            s += g_part[i];
        #pragma unroll
        for (int o = 16; o > 0; o >>= 1)
            s += __shfl_down_sync(0xffffffffu, s, o);
        if (lane == 0) smem[warp] = s;
        __syncthreads();
        if (threadIdx.x == 0) {
            double tot = smem[0] + smem[1] + smem[2] + smem[3]
                       + smem[4] + smem[5] + smem[6] + smem[7];
            g_mean  = (float)(tot * (1.0 / (double)N_TOT));
            g_count = 0;                              // replay-safe reset
        }
    }
}

// ---------------------------------------------------------------------------
// Kernel 2: warp-per-row. 8 warps/block = 8 rows, grid = 1024 blocks.
// Each lane owns 8 float4s of the 1024-wide row (MLP=8 front-batched loads,
// L2 hits since k_sum just streamed xf through L2). Sum-of-squares reduced
// with 5 shfl_xor (no smem, no __syncthreads). In-place scale, then 64
// coalesced streaming float4 stores per lane (8 tiled copies).
// ---------------------------------------------------------------------------
__global__ __launch_bounds__(256) void k_main(const float* __restrict__ xf,
                                              const float* __restrict__ wp,
                                              float* __restrict__ out) {
    const float mean = g_mean;
    const int lane = threadIdx.x & 31;
    const int warp = threadIdx.x >> 5;
    const int row  = blockIdx.x * 8 + warp;

    const float4* __restrict__ xr =
        reinterpret_cast<const float4*>(xf + (size_t)row * D_DIM);

    float4 v[8];
    #pragma unroll
    for (int i = 0; i < 8; i++)
        v[i] = __ldg(&xr[i * 32 + lane]);

    float ss = 0.0f;
    #pragma unroll
    for (int i = 0; i < 8; i++) {
        v[i].x = fmaxf(v[i].x - mean, 0.0f);
        v[i].y = fmaxf(v[i].y - mean, 0.0f);
        v[i].z = fmaxf(v[i].z - mean, 0.0f);
        v[i].w = fmaxf(v[i].w - mean, 0.0f);
        ss += v[i].x * v[i].x + v[i].y * v[i].y
            + v[i].z * v[i].z + v[i].w * v[i].w;
    }

    // butterfly reduce: every lane ends with the row total
    #pragma unroll
    for (int o = 16; o > 0; o >>= 1)
        ss += __shfl_xor_sync(0xffffffffu, ss, o);

    const float norm  = fmaxf(sqrtf(ss), EPS);
    const float sig   = 1.0f / (1.0f + __expf(-wp[0]));
    const float scale = sig / norm;

    #pragma unroll
    for (int i = 0; i < 8; i++) {
        v[i].x *= scale; v[i].y *= scale;
        v[i].z *= scale; v[i].w *= scale;
    }

    // out row = 8192 floats = 2048 float4s = 8 tiled copies of 256 float4s.
    // Streaming stores: 256 MB write-once -> keep xf resident in L2.
    float4* __restrict__ orow =
        reinterpret_cast<float4*>(out + (size_t)row * OUT_ROW);
    #pragma unroll
    for (int g = 0; g < G_REP; g++) {
        #pragma unroll
        for (int i = 0; i < 8; i++) {
            __stcs(&orow[g * 256 + i * 32 + lane], v[i]);
        }
    }
}

// ---------------------------------------------------------------------------
extern "C" void kernel_launch(void* const* d_in, const int* in_sizes, int n_in,
                              void* d_out, int out_size) {
    const float* xf = (const float*)d_in[0];
    const float* wp = (const float*)d_in[1];
    // d_in[2] is W_tile == kron(ones(1,8), eye(D)): the matmul is a pure 8x
    // tiling of fn_xf, so W_tile is never read.
    float* out = (float*)d_out;

    k_sum<<<SUM_BLOCKS, 256>>>(xf);
    k_main<<<B_ROWS / 8, 256>>>(xf, wp, out);
}